// round 4
// baseline (speedup 1.0000x reference)
#include <cuda_runtime.h>

// ---------------------------------------------------------------------------
// Decoder step: attention (B=128, L=2048, H=256) + 2x LSTM cell.
//
// mega_kernel   : blocks 0-511 = split-K flash attention (HBM-bound);
//                 blocks 512-767 = partial-gate GEMMs (FMA-bound) for the
//                 attention-independent LSTM contributions:
//                   lstm1: h_prev @ w_hh1^T          (K=256) -> g_gates1
//                   lstm2: [embed]@w_ih2[:, :256]^T
//                          + hidden2 @ w_hh2^T       (K=512) -> g_gates2
//                 (biases folded in). The FMA blocks overlap the attn tail.
// combine_kernel: merges 4 attn splits per batch -> ctx^T.
// lstm finish   : K=256 GEMM (ctx^T @ w_ih1 / h1^T @ w_ih2[:,256:512])
//                 + g_gates + fused sigmoid/tanh epilogue.
// ---------------------------------------------------------------------------

#define B_ 128
#define H_ 256
#define L_ 2048
#define NSPLIT 4
#define LSP (L_ / NSPLIT)
#define ATTN_BLOCKS (B_ * NSPLIT)   // 512

__device__ float g_ctxT[256 * 128];
__device__ float g_h1T[256 * 128];
__device__ float g_gates1[1024 * 128];
__device__ float g_gates2[1024 * 128];
__device__ float g_ctx_part[B_ * NSPLIT * H_];
__device__ float g_md[B_ * NSPLIT * 2];

// ---------------- attention helpers -----------------------------------------

__device__ __forceinline__ void online_step(
    const float4& ea, const float4& eb, const float4& ha, const float4& hb,
    float& m, float& d, float* c)
{
    float s = ea.x * ha.x + ea.y * ha.y + ea.z * ha.z + ea.w * ha.w
            + eb.x * hb.x + eb.y * hb.y + eb.z * hb.z + eb.w * hb.w;
#pragma unroll
    for (int off = 16; off; off >>= 1)
        s += __shfl_xor_sync(0xffffffffu, s, off);
    float mn = fmaxf(m, s);
    float es = __expf(s - mn);
    float em = __expf(m - mn);
    d = d * em + es;
    c[0] = fmaf(c[0], em, es * ea.x);
    c[1] = fmaf(c[1], em, es * ea.y);
    c[2] = fmaf(c[2], em, es * ea.z);
    c[3] = fmaf(c[3], em, es * ea.w);
    c[4] = fmaf(c[4], em, es * eb.x);
    c[5] = fmaf(c[5], em, es * eb.y);
    c[6] = fmaf(c[6], em, es * eb.z);
    c[7] = fmaf(c[7], em, es * eb.w);
    m = mn;
}

__device__ __forceinline__ float sigmoidf_(float x) {
    return 1.f / (1.f + __expf(-x));
}

__device__ __forceinline__ void cp_async16(void* smem_dst, const void* gmem_src) {
    unsigned saddr = (unsigned)__cvta_generic_to_shared(smem_dst);
    asm volatile("cp.async.cg.shared.global [%0], [%1], 16;\n"
                 :: "r"(saddr), "l"(gmem_src));
}
__device__ __forceinline__ void cp_commit() {
    asm volatile("cp.async.commit_group;\n");
}
__device__ __forceinline__ void cp_wait0() {
    asm volatile("cp.async.wait_group 0;\n");
}

// ---------------- mega kernel ------------------------------------------------

__global__ __launch_bounds__(256, 2) void mega_kernel(
    const float* __restrict__ enc,
    const float* __restrict__ hidden1,
    const float* __restrict__ embed,
    const float* __restrict__ hidden2,
    const float* __restrict__ w_hh1,
    const float* __restrict__ w_ih2,
    const float* __restrict__ w_hh2,
    const float* __restrict__ b_ih1, const float* __restrict__ b_hh1,
    const float* __restrict__ b_ih2, const float* __restrict__ b_hh2)
{
    extern __shared__ float smem_f[];   // 12288 floats (48 KB)
    const int bxg = blockIdx.x;
    const int tid  = threadIdx.x;
    const int warp = tid >> 5;
    const int lane = tid & 31;

    if (bxg < ATTN_BLOCKS) {
        // ---------------- attention block ----------------
        const int b  = bxg >> 2;
        const int sp = bxg & 3;

        float* h1s   = smem_f;            // [256]
        float* ctx_s = smem_f + 256;      // [8][256]
        float* m_s   = smem_f + 256 + 2048;
        float* d_s   = m_s + 8;

        h1s[tid] = hidden1[b * H_ + tid];
        __syncthreads();

        const float4 ha = *reinterpret_cast<const float4*>(&h1s[lane * 4]);
        const float4 hb = *reinterpret_cast<const float4*>(&h1s[128 + lane * 4]);

        const float* encb = enc + (size_t)b * (L_ * H_) + (size_t)sp * (LSP * H_);

        float m[4], d[4], c[4][8];
        float4 ea[4], eb[4];
        const float* p[4];
#pragma unroll
        for (int j = 0; j < 4; j++) {
            m[j] = -1e30f; d[j] = 0.f;
#pragma unroll
            for (int q = 0; q < 8; q++) c[j][q] = 0.f;
            p[j]  = encb + (size_t)(warp + 8 * j) * H_ + lane * 4;
            ea[j] = *reinterpret_cast<const float4*>(p[j]);
            eb[j] = *reinterpret_cast<const float4*>(p[j] + 128);
        }

        const int STRIDE = 32 * H_;
        const int ITERS  = LSP / 32;
        for (int i = 0; i < ITERS - 1; i++) {
            float4 na[4], nb[4];
#pragma unroll
            for (int j = 0; j < 4; j++) {
                na[j] = *reinterpret_cast<const float4*>(p[j] + STRIDE);
                nb[j] = *reinterpret_cast<const float4*>(p[j] + STRIDE + 128);
            }
#pragma unroll
            for (int j = 0; j < 4; j++)
                online_step(ea[j], eb[j], ha, hb, m[j], d[j], c[j]);
#pragma unroll
            for (int j = 0; j < 4; j++) {
                ea[j] = na[j]; eb[j] = nb[j]; p[j] += STRIDE;
            }
        }
#pragma unroll
        for (int j = 0; j < 4; j++)
            online_step(ea[j], eb[j], ha, hb, m[j], d[j], c[j]);

#pragma unroll
        for (int j = 1; j < 4; j++) {
            float M2 = fmaxf(m[0], m[j]);
            float e0 = __expf(m[0] - M2);
            float e1 = __expf(m[j] - M2);
            d[0] = d[0] * e0 + d[j] * e1;
#pragma unroll
            for (int q = 0; q < 8; q++)
                c[0][q] = c[0][q] * e0 + c[j][q] * e1;
            m[0] = M2;
        }

#pragma unroll
        for (int q = 0; q < 4; q++) {
            ctx_s[warp * 256 + lane * 4 + q]       = c[0][q];
            ctx_s[warp * 256 + 128 + lane * 4 + q] = c[0][4 + q];
        }
        if (lane == 0) { m_s[warp] = m[0]; d_s[warp] = d[0]; }
        __syncthreads();

        float M = m_s[0];
#pragma unroll
        for (int ww = 1; ww < 8; ww++) M = fmaxf(M, m_s[ww]);
        float D = 0.f, C = 0.f;
#pragma unroll
        for (int ww = 0; ww < 8; ww++) {
            float e = __expf(m_s[ww] - M);
            D += d_s[ww] * e;
            C += ctx_s[ww * 256 + tid] * e;
        }
        g_ctx_part[bxg * H_ + tid] = C;
        if (tid == 0) { g_md[bxg * 2] = M; g_md[bxg * 2 + 1] = D; }

    } else {
        // ---------------- partial-gate block ----------------
        const int gbid = bxg - ATTN_BLOCKS;     // 0..255
        const bool is2 = (gbid >= 128);
        const int  gb  = is2 ? gbid - 128 : gbid;
        const int  h0  = gb * 2;
        const int  KP  = is2 ? 512 : 256;

        float* Ws = smem_f;                  // [8][KP]
        float* Xs = smem_f + 8 * 512;        // [64][128] chunk buffer / reduce

        const int b0 = lane * 4;

        // W preload (coalesced over k)
        const int K4 = KP / 4;
        for (int idx = tid; idx < 8 * K4; idx += 256) {
            int r = idx / K4;
            int k = (idx - r * K4) * 4;
            int grow = (r & 3) * H_ + h0 + (r >> 2);
            float4 v;
            if (!is2) {
                v = *reinterpret_cast<const float4*>(&w_hh1[(size_t)grow * 256 + k]);
            } else if (k < 256) {
                v = *reinterpret_cast<const float4*>(&w_ih2[(size_t)grow * 512 + k]);
            } else {
                v = *reinterpret_cast<const float4*>(&w_hh2[(size_t)grow * 256 + (k - 256)]);
            }
            *reinterpret_cast<float4*>(&Ws[r * KP + k]) = v;
        }

        float acc[4][8];
#pragma unroll
        for (int j = 0; j < 4; j++)
#pragma unroll
            for (int r = 0; r < 8; r++) acc[j][r] = 0.f;

        const int NCH = KP / 64;
        const int bb  = tid & 127;
        const int kh  = (tid >> 7) * 32;

        for (int c = 0; c < NCH; c++) {
            // transpose-on-load: thread covers row b, 32 consecutive k
            const int kb = c * 64 + kh;
            const float* src;
            if (!is2)           src = hidden1 + bb * H_ + kb;
            else if (kb < 256)  src = embed   + bb * H_ + kb;
            else                src = hidden2 + bb * H_ + (kb - 256);

            __syncthreads();   // protect Xs vs previous compute (and Ws 1st iter)
#pragma unroll
            for (int i = 0; i < 8; i++) {
                float4 v = *reinterpret_cast<const float4*>(src + i * 4);
                int kl = kh + i * 4;
                Xs[(kl + 0) * 128 + bb] = v.x;
                Xs[(kl + 1) * 128 + bb] = v.y;
                Xs[(kl + 2) * 128 + bb] = v.z;
                Xs[(kl + 3) * 128 + bb] = v.w;
            }
            __syncthreads();

            // compute warp k-slice [warp*8, warp*8+8)
            const float* xb = Xs + (warp * 8) * 128;
            const int kg = c * 64 + warp * 8;
#pragma unroll
            for (int g2 = 0; g2 < 2; g2++) {
                float4 xv[4];
#pragma unroll
                for (int kk = 0; kk < 4; kk++)
                    xv[kk] = *reinterpret_cast<const float4*>(
                        &xb[(g2 * 4 + kk) * 128 + b0]);
                float wv[8][4];
#pragma unroll
                for (int r = 0; r < 8; r++)
                    *reinterpret_cast<float4*>(wv[r]) =
                        *reinterpret_cast<const float4*>(&Ws[r * KP + kg + g2 * 4]);
#pragma unroll
                for (int kk = 0; kk < 4; kk++) {
#pragma unroll
                    for (int r = 0; r < 8; r++) {
                        acc[0][r] = fmaf(xv[kk].x, wv[r][kk], acc[0][r]);
                        acc[1][r] = fmaf(xv[kk].y, wv[r][kk], acc[1][r]);
                        acc[2][r] = fmaf(xv[kk].z, wv[r][kk], acc[2][r]);
                        acc[3][r] = fmaf(xv[kk].w, wv[r][kk], acc[3][r]);
                    }
                }
            }
        }

        // cross-warp reduce via Xs
        __syncthreads();
#pragma unroll
        for (int r = 0; r < 8; r++)
#pragma unroll
            for (int j = 0; j < 4; j++)
                Xs[r * 1024 + warp * 128 + b0 + j] = acc[j][r];
        __syncthreads();

        float* gg = is2 ? g_gates2 : g_gates1;
        const float* bi = is2 ? b_ih2 : b_ih1;
        const float* bh = is2 ? b_hh2 : b_hh1;
        for (int e = tid; e < 1024; e += 256) {
            int r = e >> 7, b = e & 127;
            float s = 0.f;
#pragma unroll
            for (int w = 0; w < 8; w++)
                s += Xs[r * 1024 + w * 128 + b];
            int grow = (r & 3) * H_ + h0 + (r >> 2);
            gg[grow * 128 + b] = s + bi[grow] + bh[grow];
        }
    }
}

// ---------------- split combine (ctx only) ----------------------------------

__global__ __launch_bounds__(256) void combine_kernel()
{
    const int b = blockIdx.x;
    const int h = threadIdx.x;

    float ms[NSPLIT], ds[NSPLIT];
#pragma unroll
    for (int s = 0; s < NSPLIT; s++) {
        ms[s] = g_md[(b * NSPLIT + s) * 2];
        ds[s] = g_md[(b * NSPLIT + s) * 2 + 1];
    }
    float M = ms[0];
#pragma unroll
    for (int s = 1; s < NSPLIT; s++) M = fmaxf(M, ms[s]);
    float D = 0.f, C = 0.f;
#pragma unroll
    for (int s = 0; s < NSPLIT; s++) {
        float e = __expf(ms[s] - M);
        D += ds[s] * e;
        C += g_ctx_part[(b * NSPLIT + s) * H_ + h] * e;
    }
    g_ctxT[h * B_ + b] = C / D;
}

// ---------------- LSTM finish (K=256 GEMM + epilogue) ------------------------

// Block: 8 gate-rows (2 h x 4 gates) x 128 b. Warps split K 8-ways.
template <int LAYER>
__global__ __launch_bounds__(256, 1) void lstm_finish(
    const float* __restrict__ w_ih,     // lstm1: w_ih1 ; lstm2: w_ih2
    const float* __restrict__ c_prev,
    float* __restrict__ h_out, float* __restrict__ c_out,
    float* __restrict__ h_dup)
{
    constexpr int K  = 256;
    constexpr int KC = 64;
    constexpr int NC = K / KC;

    extern __shared__ float smem[];
    float* Ws = smem;                 // [8][256]
    float* Xs = smem + 8 * K;         // [2][KC*128]
    float* Rs = Xs;                   // overlay after mainloop

    const float* __restrict__ XT = (LAYER == 1) ? g_ctxT : g_h1T;
    const float* __restrict__ GG = (LAYER == 1) ? g_gates1 : g_gates2;

    const int tid  = threadIdx.x;
    const int warp = tid >> 5;
    const int lane = tid & 31;
    const int b0   = lane * 4;
    const int h0   = blockIdx.x * 2;

    // preload W tile: 8 rows x 256
    {
        for (int idx = tid; idx < 8 * 64; idx += 256) {
            int r = idx / 64;
            int k = (idx - r * 64) * 4;
            int grow = (r & 3) * H_ + h0 + (r >> 2);
            float4 v = (LAYER == 1)
                ? *reinterpret_cast<const float4*>(&w_ih[(size_t)grow * 256 + k])
                : *reinterpret_cast<const float4*>(&w_ih[(size_t)grow * 512 + 256 + k]);
            *reinterpret_cast<float4*>(&Ws[r * K + k]) = v;
        }
    }

    // prologue: async-load chunk 0
    {
        const float* src = XT + tid * 4;
        float* dst = Xs + tid * 4;
#pragma unroll
        for (int it = 0; it < (KC * 128) / (256 * 4); it++)
            cp_async16(dst + it * 1024, src + it * 1024);
        cp_commit();
    }

    float acc[4][8];
#pragma unroll
    for (int j = 0; j < 4; j++)
#pragma unroll
        for (int r = 0; r < 8; r++) acc[j][r] = 0.f;

    for (int c = 0; c < NC; c++) {
        const int buf = c & 1;
        cp_wait0();
        __syncthreads();

        if (c + 1 < NC) {
            const float* src = XT + (size_t)(c + 1) * KC * 128 + tid * 4;
            float* dst = Xs + (buf ^ 1) * (KC * 128) + tid * 4;
#pragma unroll
            for (int it = 0; it < (KC * 128) / (256 * 4); it++)
                cp_async16(dst + it * 1024, src + it * 1024);
            cp_commit();
        }

        const float* xb = Xs + buf * (KC * 128) + (warp * 8) * 128;
        const int kg = c * KC + warp * 8;
#pragma unroll
        for (int g2 = 0; g2 < 2; g2++) {
            float4 xv[4];
#pragma unroll
            for (int kk = 0; kk < 4; kk++)
                xv[kk] = *reinterpret_cast<const float4*>(
                    &xb[(g2 * 4 + kk) * 128 + b0]);
            float wv[8][4];
#pragma unroll
            for (int r = 0; r < 8; r++)
                *reinterpret_cast<float4*>(wv[r]) =
                    *reinterpret_cast<const float4*>(&Ws[r * K + kg + g2 * 4]);
#pragma unroll
            for (int kk = 0; kk < 4; kk++) {
#pragma unroll
                for (int r = 0; r < 8; r++) {
                    acc[0][r] = fmaf(xv[kk].x, wv[r][kk], acc[0][r]);
                    acc[1][r] = fmaf(xv[kk].y, wv[r][kk], acc[1][r]);
                    acc[2][r] = fmaf(xv[kk].z, wv[r][kk], acc[2][r]);
                    acc[3][r] = fmaf(xv[kk].w, wv[r][kk], acc[3][r]);
                }
            }
        }
    }

    // cross-warp reduce via smem
    __syncthreads();
#pragma unroll
    for (int r = 0; r < 8; r++)
#pragma unroll
        for (int j = 0; j < 4; j++)
            Rs[r * 1024 + warp * 128 + b0 + j] = acc[j][r];
    __syncthreads();

    // epilogue: thread = (b, hl)
    {
        const int b  = tid & 127;
        const int hl = tid >> 7;
        const int h  = h0 + hl;
        float gate[4];
#pragma unroll
        for (int g = 0; g < 4; g++) {
            float s = GG[(g * H_ + h) * 128 + b];
#pragma unroll
            for (int w = 0; w < 8; w++)
                s += Rs[(hl * 4 + g) * 1024 + w * 128 + b];
            gate[g] = s;
        }
        float gi = sigmoidf_(gate[0]);
        float gf = sigmoidf_(gate[1]);
        float gg = tanhf(gate[2]);
        float go = sigmoidf_(gate[3]);
        float cn = fmaf(gf, c_prev[b * H_ + h], gi * gg);
        float hn = go * tanhf(cn);
        c_out[b * H_ + h] = cn;
        h_out[b * H_ + h] = hn;
        if (LAYER == 1) g_h1T[h * B_ + b] = hn;
        if (h_dup)      h_dup[b * H_ + h] = hn;
    }
}

// ---------------- launch -----------------------------------------------------

extern "C" void kernel_launch(void* const* d_in, const int* in_sizes, int n_in,
                              void* d_out, int out_size)
{
    const float* embed   = (const float*)d_in[0];
    const float* enc     = (const float*)d_in[1];
    const float* hidden1 = (const float*)d_in[2];
    const float* cell1   = (const float*)d_in[3];
    const float* hidden2 = (const float*)d_in[4];
    const float* cell2   = (const float*)d_in[5];
    const float* w_ih1   = (const float*)d_in[6];
    const float* w_hh1   = (const float*)d_in[7];
    const float* b_ih1   = (const float*)d_in[8];
    const float* b_hh1   = (const float*)d_in[9];
    const float* w_ih2   = (const float*)d_in[10];
    const float* w_hh2   = (const float*)d_in[11];
    const float* b_ih2   = (const float*)d_in[12];
    const float* b_hh2   = (const float*)d_in[13];
    float* out = (float*)d_out;

    float* o_outputs = out;
    float* o_h1 = out + 32768;
    float* o_c1 = out + 65536;
    float* o_h2 = out + 98304;
    float* o_c2 = out + 131072;

    const int smem_mega  = (8 * 512 + 64 * 128) * 4;        // 49152
    const int smem_fin   = (8 * 256 + 2 * 64 * 128) * 4;    // 73728
    static bool attr_set = false;
    if (!attr_set) {
        cudaFuncSetAttribute(mega_kernel,
            cudaFuncAttributeMaxDynamicSharedMemorySize, smem_mega);
        cudaFuncSetAttribute(lstm_finish<1>,
            cudaFuncAttributeMaxDynamicSharedMemorySize, smem_fin);
        cudaFuncSetAttribute(lstm_finish<2>,
            cudaFuncAttributeMaxDynamicSharedMemorySize, smem_fin);
        attr_set = true;
    }

    mega_kernel<<<ATTN_BLOCKS + 256, 256, smem_mega>>>(
        enc, hidden1, embed, hidden2,
        w_hh1, w_ih2, w_hh2, b_ih1, b_hh1, b_ih2, b_hh2);
    combine_kernel<<<B_, 256>>>();
    lstm_finish<1><<<128, 256, smem_fin>>>(w_ih1, cell1, o_h1, o_c1, nullptr);
    lstm_finish<2><<<128, 256, smem_fin>>>(w_ih2, cell2, o_h2, o_c2, o_outputs);
}

// round 5
// speedup vs baseline: 1.0515x; 1.0515x over previous
#include <cuda_runtime.h>

// ---------------------------------------------------------------------------
// Decoder step: attention (B=128, L=2048, H=256) + 2x LSTM cell.
//
// attn_kernel   : split-K flash softmax, grid = 128 x 4 splits (HBM-bound).
//                 Also resets the chained kernel's spin-barrier counters.
// chained_kernel: grid = 384, one launch, 3 overlapped phases with
//                 device-scope spin barriers:
//                   blk 0-127  : combine splits -> g_ctxT, signal bar0
//                   blk 128-255: lstm1 = [hidden1 partial while waiting]
//                                + bar0 + ctx partial + epilogue -> g_h1T,
//                                signal bar1
//                   blk 256-383: lstm2 = [embed+hidden2 partial while waiting]
//                                + bar1 + h1 partial + epilogue
// ---------------------------------------------------------------------------

#define B_ 128
#define H_ 256
#define L_ 2048
#define NSPLIT 4
#define LSP (L_ / NSPLIT)
#define ATTN_BLOCKS (B_ * NSPLIT)   // 512

__device__ float g_ctxT[256 * 128];
__device__ float g_h1T[256 * 128];
__device__ float g_ctx_part[B_ * NSPLIT * H_];
__device__ float g_md[B_ * NSPLIT * 2];
__device__ unsigned g_bar0;
__device__ unsigned g_bar1;

// ---------------- helpers ----------------------------------------------------

__device__ __forceinline__ void online_step(
    const float4& ea, const float4& eb, const float4& ha, const float4& hb,
    float& m, float& d, float* c)
{
    float s = ea.x * ha.x + ea.y * ha.y + ea.z * ha.z + ea.w * ha.w
            + eb.x * hb.x + eb.y * hb.y + eb.z * hb.z + eb.w * hb.w;
#pragma unroll
    for (int off = 16; off; off >>= 1)
        s += __shfl_xor_sync(0xffffffffu, s, off);
    float mn = fmaxf(m, s);
    float es = __expf(s - mn);
    float em = __expf(m - mn);
    d = d * em + es;
    c[0] = fmaf(c[0], em, es * ea.x);
    c[1] = fmaf(c[1], em, es * ea.y);
    c[2] = fmaf(c[2], em, es * ea.z);
    c[3] = fmaf(c[3], em, es * ea.w);
    c[4] = fmaf(c[4], em, es * eb.x);
    c[5] = fmaf(c[5], em, es * eb.y);
    c[6] = fmaf(c[6], em, es * eb.z);
    c[7] = fmaf(c[7], em, es * eb.w);
    m = mn;
}

__device__ __forceinline__ float sigmoidf_(float x) {
    return 1.f / (1.f + __expf(-x));
}

__device__ __forceinline__ void cp_async16(void* smem_dst, const void* gmem_src) {
    unsigned saddr = (unsigned)__cvta_generic_to_shared(smem_dst);
    asm volatile("cp.async.cg.shared.global [%0], [%1], 16;\n"
                 :: "r"(saddr), "l"(gmem_src));
}
__device__ __forceinline__ void cp_commit() {
    asm volatile("cp.async.commit_group;\n");
}
__device__ __forceinline__ void cp_wait0() {
    asm volatile("cp.async.wait_group 0;\n");
}

// ---------------- attention ---------------------------------------------------

__global__ __launch_bounds__(256, 2) void attn_kernel(
    const float* __restrict__ enc,
    const float* __restrict__ hidden1)
{
    const int bx   = blockIdx.x;
    const int tid  = threadIdx.x;
    const int w    = tid >> 5;
    const int lane = tid & 31;

    if (bx == 0 && tid == 0) { g_bar0 = 0u; g_bar1 = 0u; }

    const int b  = bx >> 2;
    const int sp = bx & 3;

    __shared__ float h1s[H_];
    __shared__ float ctx_s[8][H_];
    __shared__ float m_s[8], d_s[8];

    h1s[tid] = hidden1[b * H_ + tid];
    __syncthreads();

    const float4 ha = *reinterpret_cast<const float4*>(&h1s[lane * 4]);
    const float4 hb = *reinterpret_cast<const float4*>(&h1s[128 + lane * 4]);

    const float* encb = enc + (size_t)b * (L_ * H_) + (size_t)sp * (LSP * H_);

    float m[4], d[4], c[4][8];
    float4 ea[4], eb[4];
    const float* p[4];
#pragma unroll
    for (int j = 0; j < 4; j++) {
        m[j] = -1e30f; d[j] = 0.f;
#pragma unroll
        for (int q = 0; q < 8; q++) c[j][q] = 0.f;
        p[j]  = encb + (size_t)(w + 8 * j) * H_ + lane * 4;
        ea[j] = *reinterpret_cast<const float4*>(p[j]);
        eb[j] = *reinterpret_cast<const float4*>(p[j] + 128);
    }

    const int STRIDE = 32 * H_;
    const int ITERS  = LSP / 32;
    for (int i = 0; i < ITERS - 1; i++) {
        float4 na[4], nb[4];
#pragma unroll
        for (int j = 0; j < 4; j++) {
            na[j] = *reinterpret_cast<const float4*>(p[j] + STRIDE);
            nb[j] = *reinterpret_cast<const float4*>(p[j] + STRIDE + 128);
        }
#pragma unroll
        for (int j = 0; j < 4; j++)
            online_step(ea[j], eb[j], ha, hb, m[j], d[j], c[j]);
#pragma unroll
        for (int j = 0; j < 4; j++) {
            ea[j] = na[j]; eb[j] = nb[j]; p[j] += STRIDE;
        }
    }
#pragma unroll
    for (int j = 0; j < 4; j++)
        online_step(ea[j], eb[j], ha, hb, m[j], d[j], c[j]);

#pragma unroll
    for (int j = 1; j < 4; j++) {
        float M2 = fmaxf(m[0], m[j]);
        float e0 = __expf(m[0] - M2);
        float e1 = __expf(m[j] - M2);
        d[0] = d[0] * e0 + d[j] * e1;
#pragma unroll
        for (int q = 0; q < 8; q++)
            c[0][q] = c[0][q] * e0 + c[j][q] * e1;
        m[0] = M2;
    }

#pragma unroll
    for (int q = 0; q < 4; q++) {
        ctx_s[w][lane * 4 + q]       = c[0][q];
        ctx_s[w][128 + lane * 4 + q] = c[0][4 + q];
    }
    if (lane == 0) { m_s[w] = m[0]; d_s[w] = d[0]; }
    __syncthreads();

    float M = m_s[0];
#pragma unroll
    for (int ww = 1; ww < 8; ww++) M = fmaxf(M, m_s[ww]);
    float D = 0.f, C = 0.f;
#pragma unroll
    for (int ww = 0; ww < 8; ww++) {
        float e = __expf(m_s[ww] - M);
        D += d_s[ww] * e;
        C += ctx_s[ww][tid] * e;
    }
    g_ctx_part[bx * H_ + tid] = C;
    if (tid == 0) { g_md[bx * 2] = M; g_md[bx * 2 + 1] = D; }
}

// ---------------- chained combine + lstm1 + lstm2 -----------------------------

// smem: Ws (up to 8x768 = 6144 floats) then Xs (8192 floats).
#define WS_FLOATS 6144
#define XS_FLOATS 8192
#define SMEM_FLOATS (WS_FLOATS + XS_FLOATS)

__global__ __launch_bounds__(256, 2) void chained_kernel(
    const float* __restrict__ embed,
    const float* __restrict__ hidden1,
    const float* __restrict__ hidden2,
    const float* __restrict__ cell1,
    const float* __restrict__ cell2,
    const float* __restrict__ w_ih1, const float* __restrict__ w_hh1,
    const float* __restrict__ b_ih1, const float* __restrict__ b_hh1,
    const float* __restrict__ w_ih2, const float* __restrict__ w_hh2,
    const float* __restrict__ b_ih2, const float* __restrict__ b_hh2,
    float* __restrict__ out)
{
    extern __shared__ float smem[];
    const int bid  = blockIdx.x;
    const int tid  = threadIdx.x;
    const int warp = tid >> 5;
    const int lane = tid & 31;

    // ---------------- phase 0: combine blocks --------------------------------
    if (bid < 128) {
        const int b = bid;
        const int h = tid;
        float ms[NSPLIT], ds[NSPLIT];
#pragma unroll
        for (int s = 0; s < NSPLIT; s++) {
            ms[s] = g_md[(b * NSPLIT + s) * 2];
            ds[s] = g_md[(b * NSPLIT + s) * 2 + 1];
        }
        float M = ms[0];
#pragma unroll
        for (int s = 1; s < NSPLIT; s++) M = fmaxf(M, ms[s]);
        float D = 0.f, C = 0.f;
#pragma unroll
        for (int s = 0; s < NSPLIT; s++) {
            float e = __expf(ms[s] - M);
            D += ds[s] * e;
            C += g_ctx_part[(b * NSPLIT + s) * H_ + h] * e;
        }
        g_ctxT[h * B_ + b] = C / D;
        __threadfence();
        __syncthreads();
        if (tid == 0) atomicAdd(&g_bar0, 1u);
        return;
    }

    // ---------------- lstm blocks ---------------------------------------------
    const bool lay2 = (bid >= 256);
    const int  h0   = (lay2 ? bid - 256 : bid - 128) * 2;
    const int  K    = lay2 ? 768 : 512;

    float* Ws = smem;
    float* Xs = smem + WS_FLOATS;

    const int b0 = lane * 4;

    // W preload: 8 gate rows x K. lstm1: [0,256)=w_ih1, [256,512)=w_hh1.
    // lstm2: [0,512)=w_ih2 (embed cols 0-255, h1 cols 256-511), [512,768)=w_hh2.
    {
        const int K4 = K / 4;
        for (int idx = tid; idx < 8 * K4; idx += 256) {
            int r = idx / K4;
            int k = (idx - r * K4) * 4;
            int grow = (r & 3) * H_ + h0 + (r >> 2);
            float4 v;
            if (!lay2) {
                v = (k < 256)
                    ? *reinterpret_cast<const float4*>(&w_ih1[(size_t)grow * 256 + k])
                    : *reinterpret_cast<const float4*>(&w_hh1[(size_t)grow * 256 + (k - 256)]);
            } else {
                v = (k < 512)
                    ? *reinterpret_cast<const float4*>(&w_ih2[(size_t)grow * 512 + k])
                    : *reinterpret_cast<const float4*>(&w_hh2[(size_t)grow * 256 + (k - 512)]);
            }
            *reinterpret_cast<float4*>(&Ws[r * K + k]) = v;
        }
    }

    float acc[4][8];
#pragma unroll
    for (int j = 0; j < 4; j++)
#pragma unroll
        for (int r = 0; r < 8; r++) acc[j][r] = 0.f;

    // ---------- phase A: attention-independent partial (transpose-on-load) ----
    {
        const int bb = tid & 127;
        const int kh = (tid >> 7) * 32;
        const int NCA = lay2 ? 8 : 4;

        for (int c = 0; c < NCA; c++) {
            const float* src;
            int wsoff;
            if (!lay2)      { src = hidden1 + bb * H_ + c * 64 + kh;       wsoff = 256 + c * 64; }
            else if (c < 4) { src = embed   + bb * H_ + c * 64 + kh;       wsoff = c * 64; }
            else            { src = hidden2 + bb * H_ + (c - 4) * 64 + kh; wsoff = 512 + (c - 4) * 64; }

            __syncthreads();
#pragma unroll
            for (int i = 0; i < 8; i++) {
                float4 v = *reinterpret_cast<const float4*>(src + i * 4);
                int kl = kh + i * 4;
                Xs[(kl + 0) * 128 + bb] = v.x;
                Xs[(kl + 1) * 128 + bb] = v.y;
                Xs[(kl + 2) * 128 + bb] = v.z;
                Xs[(kl + 3) * 128 + bb] = v.w;
            }
            __syncthreads();

            const float* xb = Xs + (warp * 8) * 128;
            const int kg = wsoff + warp * 8;
#pragma unroll
            for (int g2 = 0; g2 < 2; g2++) {
                float4 xv[4];
#pragma unroll
                for (int kk = 0; kk < 4; kk++)
                    xv[kk] = *reinterpret_cast<const float4*>(
                        &xb[(g2 * 4 + kk) * 128 + b0]);
                float wv[8][4];
#pragma unroll
                for (int r = 0; r < 8; r++)
                    *reinterpret_cast<float4*>(wv[r]) =
                        *reinterpret_cast<const float4*>(&Ws[r * K + kg + g2 * 4]);
#pragma unroll
                for (int kk = 0; kk < 4; kk++) {
#pragma unroll
                    for (int r = 0; r < 8; r++) {
                        acc[0][r] = fmaf(xv[kk].x, wv[r][kk], acc[0][r]);
                        acc[1][r] = fmaf(xv[kk].y, wv[r][kk], acc[1][r]);
                        acc[2][r] = fmaf(xv[kk].z, wv[r][kk], acc[2][r]);
                        acc[3][r] = fmaf(xv[kk].w, wv[r][kk], acc[3][r]);
                    }
                }
            }
        }
    }

    // ---------- wait for dependency ------------------------------------------
    if (tid == 0) {
        unsigned* bar = lay2 ? &g_bar1 : &g_bar0;
        while (atomicAdd(bar, 0u) < 128u) __nanosleep(64);
        __threadfence();
    }
    __syncthreads();

    // ---------- phase B: dependent K=256 partial via cp.async -----------------
    {
        const float* __restrict__ XT = lay2 ? g_h1T : g_ctxT;
        const int wsb = lay2 ? 256 : 0;

        // prologue: chunk 0 (32 k x 128 b = 1024 float4)
        {
            const float4* src = reinterpret_cast<const float4*>(XT);
            float4* dst = reinterpret_cast<float4*>(Xs);
#pragma unroll
            for (int it = 0; it < 4; it++)
                cp_async16(dst + it * 256 + tid, src + it * 256 + tid);
            cp_commit();
        }

        for (int c = 0; c < 8; c++) {
            cp_wait0();
            __syncthreads();

            if (c + 1 < 8) {
                const float4* src = reinterpret_cast<const float4*>(XT) + (c + 1) * 1024;
                float4* dst = reinterpret_cast<float4*>(Xs + ((c + 1) & 1) * 4096);
#pragma unroll
                for (int it = 0; it < 4; it++)
                    cp_async16(dst + it * 256 + tid, src + it * 256 + tid);
                cp_commit();
            }

            const float* xb = Xs + (c & 1) * 4096 + (warp * 4) * 128;
            const int kg = wsb + c * 32 + warp * 4;
            float4 xv[4];
#pragma unroll
            for (int kk = 0; kk < 4; kk++)
                xv[kk] = *reinterpret_cast<const float4*>(&xb[kk * 128 + b0]);
            float wv[8][4];
#pragma unroll
            for (int r = 0; r < 8; r++)
                *reinterpret_cast<float4*>(wv[r]) =
                    *reinterpret_cast<const float4*>(&Ws[r * K + kg]);
#pragma unroll
            for (int kk = 0; kk < 4; kk++) {
#pragma unroll
                for (int r = 0; r < 8; r++) {
                    acc[0][r] = fmaf(xv[kk].x, wv[r][kk], acc[0][r]);
                    acc[1][r] = fmaf(xv[kk].y, wv[r][kk], acc[1][r]);
                    acc[2][r] = fmaf(xv[kk].z, wv[r][kk], acc[2][r]);
                    acc[3][r] = fmaf(xv[kk].w, wv[r][kk], acc[3][r]);
                }
            }
        }
    }

    // ---------- cross-warp reduce + epilogue -----------------------------------
    __syncthreads();
    float* Rs = Xs;
#pragma unroll
    for (int r = 0; r < 8; r++)
#pragma unroll
        for (int j = 0; j < 4; j++)
            Rs[r * 1024 + warp * 128 + b0 + j] = acc[j][r];
    __syncthreads();

    {
        const int b  = tid & 127;
        const int hl = tid >> 7;
        const int h  = h0 + hl;
        const float* bi = lay2 ? b_ih2 : b_ih1;
        const float* bh = lay2 ? b_hh2 : b_hh1;
        const float* cp = lay2 ? cell2 : cell1;

        float gate[4];
#pragma unroll
        for (int g = 0; g < 4; g++) {
            float s = bi[g * H_ + h] + bh[g * H_ + h];
#pragma unroll
            for (int w = 0; w < 8; w++)
                s += Rs[(hl * 4 + g) * 1024 + w * 128 + b];
            gate[g] = s;
        }
        float gi = sigmoidf_(gate[0]);
        float gf = sigmoidf_(gate[1]);
        float gg = tanhf(gate[2]);
        float go = sigmoidf_(gate[3]);
        float cn = fmaf(gf, cp[b * H_ + h], gi * gg);
        float hn = go * tanhf(cn);

        if (!lay2) {
            out[65536 + b * H_ + h]  = cn;   // c1
            out[32768 + b * H_ + h]  = hn;   // h1
            g_h1T[h * B_ + b] = hn;
        } else {
            out[131072 + b * H_ + h] = cn;   // c2
            out[98304 + b * H_ + h]  = hn;   // h2
            out[b * H_ + h]          = hn;   // outputs
        }
    }

    if (!lay2) {
        __threadfence();
        __syncthreads();
        if (tid == 0) atomicAdd(&g_bar1, 1u);
    }
}

// ---------------- launch -------------------------------------------------------

extern "C" void kernel_launch(void* const* d_in, const int* in_sizes, int n_in,
                              void* d_out, int out_size)
{
    const float* embed   = (const float*)d_in[0];
    const float* enc     = (const float*)d_in[1];
    const float* hidden1 = (const float*)d_in[2];
    const float* cell1   = (const float*)d_in[3];
    const float* hidden2 = (const float*)d_in[4];
    const float* cell2   = (const float*)d_in[5];
    const float* w_ih1   = (const float*)d_in[6];
    const float* w_hh1   = (const float*)d_in[7];
    const float* b_ih1   = (const float*)d_in[8];
    const float* b_hh1   = (const float*)d_in[9];
    const float* w_ih2   = (const float*)d_in[10];
    const float* w_hh2   = (const float*)d_in[11];
    const float* b_ih2   = (const float*)d_in[12];
    const float* b_hh2   = (const float*)d_in[13];
    float* out = (float*)d_out;

    const int smem_chain = SMEM_FLOATS * 4;   // 57344
    static bool attr_set = false;
    if (!attr_set) {
        cudaFuncSetAttribute(chained_kernel,
            cudaFuncAttributeMaxDynamicSharedMemorySize, smem_chain);
        attr_set = true;
    }

    attn_kernel<<<ATTN_BLOCKS, 256>>>(enc, hidden1);
    chained_kernel<<<384, 256, smem_chain>>>(
        embed, hidden1, hidden2, cell1, cell2,
        w_ih1, w_hh1, b_ih1, b_hh1,
        w_ih2, w_hh2, b_ih2, b_hh2, out);
}

// round 6
// speedup vs baseline: 1.1340x; 1.0785x over previous
#include <cuda_runtime.h>

// ---------------------------------------------------------------------------
// Decoder step: attention (B=128, L=2048, H=256) + 2x LSTM cell.
//
// mega_kernel : bids 0-255 = gate-partial GEMMs (attention-independent LSTM
//               contributions, FMA-bound, scheduled FIRST so they overlap the
//               HBM-bound attention); bids 256-767 = split-K flash attention.
//                 gates1 = bias1 + hidden1 @ w_hh1^T              (K=256)
//                 gates2 = bias2 + embed @ w_ih2[:, :256]^T
//                               + hidden2 @ w_hh2^T               (K=512)
// combine     : merge 4 attn splits -> g_ctxT (transposed, k-major).
// finish<1>   : gates1 += ctx @ w_ih1^T, epilogue -> h1,c1, g_h1T.
// finish<2>   : gates2 += h1 @ w_ih2[:, 256:]^T, epilogue -> out,h2,c2.
//               finish: grid=256 (1 h, 4 gate rows/block), warps split K
//               8-ways, X via direct LDG.128 (no mainloop barriers).
// ---------------------------------------------------------------------------

#define B_ 128
#define H_ 256
#define L_ 2048
#define NSPLIT 4
#define LSP (L_ / NSPLIT)
#define GATE_BLOCKS 256
#define ATTN_BLOCKS (B_ * NSPLIT)   // 512

__device__ float g_ctxT[256 * 128];
__device__ float g_h1T[256 * 128];
__device__ float g_gates1[1024 * 128];
__device__ float g_gates2[1024 * 128];
__device__ float g_ctx_part[B_ * NSPLIT * H_];
__device__ float g_md[B_ * NSPLIT * 2];

// ---------------- helpers ----------------------------------------------------

__device__ __forceinline__ void online_step(
    const float4& ea, const float4& eb, const float4& ha, const float4& hb,
    float& m, float& d, float* c)
{
    float s = ea.x * ha.x + ea.y * ha.y + ea.z * ha.z + ea.w * ha.w
            + eb.x * hb.x + eb.y * hb.y + eb.z * hb.z + eb.w * hb.w;
#pragma unroll
    for (int off = 16; off; off >>= 1)
        s += __shfl_xor_sync(0xffffffffu, s, off);
    float mn = fmaxf(m, s);
    float es = __expf(s - mn);
    float em = __expf(m - mn);
    d = d * em + es;
    c[0] = fmaf(c[0], em, es * ea.x);
    c[1] = fmaf(c[1], em, es * ea.y);
    c[2] = fmaf(c[2], em, es * ea.z);
    c[3] = fmaf(c[3], em, es * ea.w);
    c[4] = fmaf(c[4], em, es * eb.x);
    c[5] = fmaf(c[5], em, es * eb.y);
    c[6] = fmaf(c[6], em, es * eb.z);
    c[7] = fmaf(c[7], em, es * eb.w);
    m = mn;
}

__device__ __forceinline__ float sigmoidf_(float x) {
    return 1.f / (1.f + __expf(-x));
}

__device__ __forceinline__ void cp_async16(void* smem_dst, const void* gmem_src) {
    unsigned saddr = (unsigned)__cvta_generic_to_shared(smem_dst);
    asm volatile("cp.async.cg.shared.global [%0], [%1], 16;\n"
                 :: "r"(saddr), "l"(gmem_src));
}
__device__ __forceinline__ void cp_commit() {
    asm volatile("cp.async.commit_group;\n");
}
__device__ __forceinline__ void cp_wait0() {
    asm volatile("cp.async.wait_group 0;\n");
}

// ---------------- mega: gate partials first, then attention -------------------

__global__ __launch_bounds__(256, 2) void mega_kernel(
    const float* __restrict__ enc,
    const float* __restrict__ hidden1,
    const float* __restrict__ embed,
    const float* __restrict__ hidden2,
    const float* __restrict__ w_hh1,
    const float* __restrict__ w_ih2,
    const float* __restrict__ w_hh2,
    const float* __restrict__ b_ih1, const float* __restrict__ b_hh1,
    const float* __restrict__ b_ih2, const float* __restrict__ b_hh2)
{
    extern __shared__ float smem_f[];   // 12288 floats (48 KB)
    const int bxg  = blockIdx.x;
    const int tid  = threadIdx.x;
    const int warp = tid >> 5;
    const int lane = tid & 31;

    if (bxg >= GATE_BLOCKS) {
        // ---------------- attention block ----------------
        const int bx = bxg - GATE_BLOCKS;
        const int b  = bx >> 2;
        const int sp = bx & 3;

        float* h1s   = smem_f;            // [256]
        float* ctx_s = smem_f + 256;      // [8][256]
        float* m_s   = smem_f + 256 + 2048;
        float* d_s   = m_s + 8;

        h1s[tid] = hidden1[b * H_ + tid];
        __syncthreads();

        const float4 ha = *reinterpret_cast<const float4*>(&h1s[lane * 4]);
        const float4 hb = *reinterpret_cast<const float4*>(&h1s[128 + lane * 4]);

        const float* encb = enc + (size_t)b * (L_ * H_) + (size_t)sp * (LSP * H_);

        float m[4], d[4], c[4][8];
        float4 ea[4], eb[4];
        const float* p[4];
#pragma unroll
        for (int j = 0; j < 4; j++) {
            m[j] = -1e30f; d[j] = 0.f;
#pragma unroll
            for (int q = 0; q < 8; q++) c[j][q] = 0.f;
            p[j]  = encb + (size_t)(warp + 8 * j) * H_ + lane * 4;
            ea[j] = *reinterpret_cast<const float4*>(p[j]);
            eb[j] = *reinterpret_cast<const float4*>(p[j] + 128);
        }

        const int STRIDE = 32 * H_;
        const int ITERS  = LSP / 32;
        for (int i = 0; i < ITERS - 1; i++) {
            float4 na[4], nb[4];
#pragma unroll
            for (int j = 0; j < 4; j++) {
                na[j] = *reinterpret_cast<const float4*>(p[j] + STRIDE);
                nb[j] = *reinterpret_cast<const float4*>(p[j] + STRIDE + 128);
            }
#pragma unroll
            for (int j = 0; j < 4; j++)
                online_step(ea[j], eb[j], ha, hb, m[j], d[j], c[j]);
#pragma unroll
            for (int j = 0; j < 4; j++) {
                ea[j] = na[j]; eb[j] = nb[j]; p[j] += STRIDE;
            }
        }
#pragma unroll
        for (int j = 0; j < 4; j++)
            online_step(ea[j], eb[j], ha, hb, m[j], d[j], c[j]);

#pragma unroll
        for (int j = 1; j < 4; j++) {
            float M2 = fmaxf(m[0], m[j]);
            float e0 = __expf(m[0] - M2);
            float e1 = __expf(m[j] - M2);
            d[0] = d[0] * e0 + d[j] * e1;
#pragma unroll
            for (int q = 0; q < 8; q++)
                c[0][q] = c[0][q] * e0 + c[j][q] * e1;
            m[0] = M2;
        }

#pragma unroll
        for (int q = 0; q < 4; q++) {
            ctx_s[warp * 256 + lane * 4 + q]       = c[0][q];
            ctx_s[warp * 256 + 128 + lane * 4 + q] = c[0][4 + q];
        }
        if (lane == 0) { m_s[warp] = m[0]; d_s[warp] = d[0]; }
        __syncthreads();

        float M = m_s[0];
#pragma unroll
        for (int ww = 1; ww < 8; ww++) M = fmaxf(M, m_s[ww]);
        float D = 0.f, C = 0.f;
#pragma unroll
        for (int ww = 0; ww < 8; ww++) {
            float e = __expf(m_s[ww] - M);
            D += d_s[ww] * e;
            C += ctx_s[ww * 256 + tid] * e;
        }
        g_ctx_part[bx * H_ + tid] = C;
        if (tid == 0) { g_md[bx * 2] = M; g_md[bx * 2 + 1] = D; }

    } else {
        // ---------------- partial-gate block ----------------
        const int gbid = bxg;                   // 0..255
        const bool is2 = (gbid >= 128);
        const int  gb  = is2 ? gbid - 128 : gbid;
        const int  h0  = gb * 2;
        const int  KP  = is2 ? 512 : 256;

        float* Ws = smem_f;                  // [8][KP]
        float* Xs = smem_f + 8 * 512;        // [64][128] chunk buffer / reduce

        const int b0 = lane * 4;

        // W preload (coalesced over k)
        const int K4 = KP / 4;
        for (int idx = tid; idx < 8 * K4; idx += 256) {
            int r = idx / K4;
            int k = (idx - r * K4) * 4;
            int grow = (r & 3) * H_ + h0 + (r >> 2);
            float4 v;
            if (!is2) {
                v = *reinterpret_cast<const float4*>(&w_hh1[(size_t)grow * 256 + k]);
            } else if (k < 256) {
                v = *reinterpret_cast<const float4*>(&w_ih2[(size_t)grow * 512 + k]);
            } else {
                v = *reinterpret_cast<const float4*>(&w_hh2[(size_t)grow * 256 + (k - 256)]);
            }
            *reinterpret_cast<float4*>(&Ws[r * KP + k]) = v;
        }

        float acc[4][8];
#pragma unroll
        for (int j = 0; j < 4; j++)
#pragma unroll
            for (int r = 0; r < 8; r++) acc[j][r] = 0.f;

        const int NCH = KP / 64;
        const int bb  = tid & 127;
        const int kh  = (tid >> 7) * 32;

        for (int c = 0; c < NCH; c++) {
            const int kb = c * 64 + kh;
            const float* src;
            if (!is2)           src = hidden1 + bb * H_ + kb;
            else if (kb < 256)  src = embed   + bb * H_ + kb;
            else                src = hidden2 + bb * H_ + (kb - 256);

            __syncthreads();
#pragma unroll
            for (int i = 0; i < 8; i++) {
                float4 v = *reinterpret_cast<const float4*>(src + i * 4);
                int kl = kh + i * 4;
                Xs[(kl + 0) * 128 + bb] = v.x;
                Xs[(kl + 1) * 128 + bb] = v.y;
                Xs[(kl + 2) * 128 + bb] = v.z;
                Xs[(kl + 3) * 128 + bb] = v.w;
            }
            __syncthreads();

            const float* xb = Xs + (warp * 8) * 128;
            const int kg = c * 64 + warp * 8;
#pragma unroll
            for (int g2 = 0; g2 < 2; g2++) {
                float4 xv[4];
#pragma unroll
                for (int kk = 0; kk < 4; kk++)
                    xv[kk] = *reinterpret_cast<const float4*>(
                        &xb[(g2 * 4 + kk) * 128 + b0]);
                float wv[8][4];
#pragma unroll
                for (int r = 0; r < 8; r++)
                    *reinterpret_cast<float4*>(wv[r]) =
                        *reinterpret_cast<const float4*>(&Ws[r * KP + kg + g2 * 4]);
#pragma unroll
                for (int kk = 0; kk < 4; kk++) {
#pragma unroll
                    for (int r = 0; r < 8; r++) {
                        acc[0][r] = fmaf(xv[kk].x, wv[r][kk], acc[0][r]);
                        acc[1][r] = fmaf(xv[kk].y, wv[r][kk], acc[1][r]);
                        acc[2][r] = fmaf(xv[kk].z, wv[r][kk], acc[2][r]);
                        acc[3][r] = fmaf(xv[kk].w, wv[r][kk], acc[3][r]);
                    }
                }
            }
        }

        __syncthreads();
#pragma unroll
        for (int r = 0; r < 8; r++)
#pragma unroll
            for (int j = 0; j < 4; j++)
                Xs[r * 1024 + warp * 128 + b0 + j] = acc[j][r];
        __syncthreads();

        float* gg = is2 ? g_gates2 : g_gates1;
        const float* bi = is2 ? b_ih2 : b_ih1;
        const float* bh = is2 ? b_hh2 : b_hh1;
        for (int e = tid; e < 1024; e += 256) {
            int r = e >> 7, b = e & 127;
            float s = 0.f;
#pragma unroll
            for (int w = 0; w < 8; w++)
                s += Xs[r * 1024 + w * 128 + b];
            int grow = (r & 3) * H_ + h0 + (r >> 2);
            gg[grow * 128 + b] = s + bi[grow] + bh[grow];
        }
    }
}

// ---------------- split combine (ctx only) ------------------------------------

__global__ __launch_bounds__(256) void combine_kernel()
{
    const int b = blockIdx.x;
    const int h = threadIdx.x;

    float ms[NSPLIT], ds[NSPLIT];
#pragma unroll
    for (int s = 0; s < NSPLIT; s++) {
        ms[s] = g_md[(b * NSPLIT + s) * 2];
        ds[s] = g_md[(b * NSPLIT + s) * 2 + 1];
    }
    float M = ms[0];
#pragma unroll
    for (int s = 1; s < NSPLIT; s++) M = fmaxf(M, ms[s]);
    float D = 0.f, C = 0.f;
#pragma unroll
    for (int s = 0; s < NSPLIT; s++) {
        float e = __expf(ms[s] - M);
        D += ds[s] * e;
        C += g_ctx_part[(b * NSPLIT + s) * H_ + h] * e;
    }
    g_ctxT[h * B_ + b] = C / D;
}

// ---------------- finish: dependent K=256 GEMM + epilogue ---------------------

// Block = 1 h-index (4 gate rows) x 128 batches. grid = 256.
// Warps split K 8-ways (32 k each). X streamed via direct LDG.128 from L2.
template <int LAYER>
__global__ __launch_bounds__(256, 2) void finish_kernel(
    const float* __restrict__ w_ih,      // L1: w_ih1 ; L2: w_ih2
    const float* __restrict__ c_prev,
    float* __restrict__ out)
{
    constexpr int RS  = (LAYER == 1) ? 256 : 512;   // w row stride
    constexpr int OFF = (LAYER == 1) ? 0 : 256;     // col offset

    __shared__ float Ws[4 * 256];        // 4 gate rows x 256 k
    __shared__ float Rs[4 * 8 * 128];    // [gate][warp][batch]

    const int tid  = threadIdx.x;
    const int warp = tid >> 5;
    const int lane = tid & 31;
    const int b0   = lane * 4;
    const int h    = blockIdx.x;

    const float* __restrict__ XT = (LAYER == 1) ? g_ctxT : g_h1T;
    const float* __restrict__ GG = (LAYER == 1) ? g_gates1 : g_gates2;

    // W prologue: 4 rows x 64 float4 = 256 transfers, one per thread
    {
        int g  = tid >> 6;
        int k4 = tid & 63;
        cp_async16(&Ws[g * 256 + k4 * 4],
                   w_ih + (size_t)(g * H_ + h) * RS + OFF + k4 * 4);
        cp_commit();
        cp_wait0();
    }
    __syncthreads();

    float acc[4][4];   // [batch j][gate g]
#pragma unroll
    for (int j = 0; j < 4; j++)
#pragma unroll
        for (int g = 0; g < 4; g++) acc[j][g] = 0.f;

    const int kbase = warp * 32;
#pragma unroll
    for (int s = 0; s < 4; s++) {
        float4 xv[8];
#pragma unroll
        for (int i = 0; i < 8; i++)
            xv[i] = *reinterpret_cast<const float4*>(
                &XT[(size_t)(kbase + s * 8 + i) * 128 + b0]);
#pragma unroll
        for (int i = 0; i < 8; i += 4) {
            float wr[4][4];
#pragma unroll
            for (int g = 0; g < 4; g++)
                *reinterpret_cast<float4*>(wr[g]) =
                    *reinterpret_cast<const float4*>(&Ws[g * 256 + kbase + s * 8 + i]);
#pragma unroll
            for (int kk = 0; kk < 4; kk++) {
                float4 x = xv[i + kk];
#pragma unroll
                for (int g = 0; g < 4; g++) {
                    acc[0][g] = fmaf(x.x, wr[g][kk], acc[0][g]);
                    acc[1][g] = fmaf(x.y, wr[g][kk], acc[1][g]);
                    acc[2][g] = fmaf(x.z, wr[g][kk], acc[2][g]);
                    acc[3][g] = fmaf(x.w, wr[g][kk], acc[3][g]);
                }
            }
        }
    }

    __syncthreads();   // Rs region is fresh smem (not overlaid), just ordering
#pragma unroll
    for (int g = 0; g < 4; g++)
#pragma unroll
        for (int j = 0; j < 4; j++)
            Rs[(g * 8 + warp) * 128 + b0 + j] = acc[j][g];
    __syncthreads();

    if (tid < 128) {
        const int b = tid;
        float gate[4];
#pragma unroll
        for (int g = 0; g < 4; g++) {
            float s = GG[(size_t)(g * H_ + h) * 128 + b];
#pragma unroll
            for (int w = 0; w < 8; w++)
                s += Rs[(g * 8 + w) * 128 + b];
            gate[g] = s;
        }
        float gi = sigmoidf_(gate[0]);
        float gf = sigmoidf_(gate[1]);
        float gg = tanhf(gate[2]);
        float go = sigmoidf_(gate[3]);
        float cn = fmaf(gf, c_prev[b * H_ + h], gi * gg);
        float hn = go * tanhf(cn);

        if (LAYER == 1) {
            out[65536 + b * H_ + h] = cn;    // c1
            out[32768 + b * H_ + h] = hn;    // h1
            g_h1T[h * B_ + b] = hn;
        } else {
            out[131072 + b * H_ + h] = cn;   // c2
            out[98304 + b * H_ + h]  = hn;   // h2
            out[b * H_ + h]          = hn;   // outputs
        }
    }
}

// ---------------- launch -------------------------------------------------------

extern "C" void kernel_launch(void* const* d_in, const int* in_sizes, int n_in,
                              void* d_out, int out_size)
{
    const float* embed   = (const float*)d_in[0];
    const float* enc     = (const float*)d_in[1];
    const float* hidden1 = (const float*)d_in[2];
    const float* cell1   = (const float*)d_in[3];
    const float* hidden2 = (const float*)d_in[4];
    const float* cell2   = (const float*)d_in[5];
    const float* w_ih1   = (const float*)d_in[6];
    const float* w_hh1   = (const float*)d_in[7];
    const float* b_ih1   = (const float*)d_in[8];
    const float* b_hh1   = (const float*)d_in[9];
    const float* w_ih2   = (const float*)d_in[10];
    const float* w_hh2   = (const float*)d_in[11];
    const float* b_ih2   = (const float*)d_in[12];
    const float* b_hh2   = (const float*)d_in[13];
    float* out = (float*)d_out;

    const int smem_mega = (8 * 512 + 64 * 128) * 4;   // 49152
    static bool attr_set = false;
    if (!attr_set) {
        cudaFuncSetAttribute(mega_kernel,
            cudaFuncAttributeMaxDynamicSharedMemorySize, smem_mega);
        attr_set = true;
    }

    mega_kernel<<<GATE_BLOCKS + ATTN_BLOCKS, 256, smem_mega>>>(
        enc, hidden1, embed, hidden2,
        w_hh1, w_ih2, w_hh2, b_ih1, b_hh1, b_ih2, b_hh2);
    combine_kernel<<<B_, 256>>>();
    finish_kernel<1><<<256, 256>>>(w_ih1, cell1, out);
    finish_kernel<2><<<256, 256>>>(w_ih2, cell2, out);
}